// round 10
// baseline (speedup 1.0000x reference)
#include <cuda_runtime.h>
#include <cstdint>
#include <math.h>

#define BB 64
#define TT 512
#define DD 256
#define HH 256
#define NTHR 256
#define NBLK 128
#define NB_N 16        // hidden dims per block
#define NB_B 16        // batches per block
#define NGRP 8         // sync groups (dir x bgrp)
#define GRPBLK 16      // blocks per sync group

// ---------------- device scratch (static allocation, allowed) ----------------
__device__ float g_xt[2][TT][4][DD][NB_B];            // [dir][t][bgrp][k][b]       64 MB
__device__ float g_xp[2][4][NB_N][TT][NB_N * NB_B * 4]; // precomputed gate pre-acts 268 MB
__device__ float g_hb[2][2][4][HH][NB_B];             // [dir][phase][bgrp][n][b]
__device__ int      g_flag[NGRP][GRPBLK];             // step flags (reset at end)
__device__ unsigned g_bcnt, g_bsns;                   // global barrier (self-stable)

// ---- fast gate math (|rel err| ~1e-6, saturation-safe) ----
__device__ __forceinline__ float fsig(float v) {
    return __fdividef(1.f, 1.f + __expf(-v));
}
__device__ __forceinline__ float ftanh(float v) {
    return 1.f - __fdividef(2.f, __expf(2.f * v) + 1.f);
}

// ---- packed fp32x2 helpers (sm_100+) ----
__device__ __forceinline__ void fmaf2(unsigned long long& d,
                                      unsigned long long a, unsigned long long b) {
    asm("fma.rn.f32x2 %0, %1, %2, %3;" : "=l"(d) : "l"(a), "l"(b), "l"(d));
}
__device__ __forceinline__ unsigned long long addf2(unsigned long long a,
                                                    unsigned long long b) {
    unsigned long long r;
    asm("add.rn.f32x2 %0, %1, %2;" : "=l"(r) : "l"(a), "l"(b));
    return r;
}
__device__ __forceinline__ void unpack2(unsigned long long v, float& lo, float& hi) {
    asm("mov.b64 {%0, %1}, %2;" : "=f"(lo), "=f"(hi) : "l"(v));
}

// ---- cp.async helpers ----
__device__ __forceinline__ void cpa16(uint32_t dst_smem, const void* src) {
    asm volatile("cp.async.cg.shared.global [%0], [%1], 16;"
                 :: "r"(dst_smem), "l"(src));
}
#define CP_COMMIT() asm volatile("cp.async.commit_group;")
#define CP_WAIT(n)  asm volatile("cp.async.wait_group %0;" :: "n"(n))

__device__ __forceinline__ uint32_t smem_u32(const void* p) {
    uint32_t a;
    asm("{ .reg .u64 t; cvta.to.shared.u64 t, %1; cvt.u32.u64 %0, t; }"
        : "=r"(a) : "l"(p));
    return a;
}

// SMEM float offsets
#define WT_F    0
#define XST_F   (256 * 128)                 // 32768
#define XPS_F   (XST_F + 2 * DD * NB_B)     // +8192
#define RED_F   (XPS_F + 2 * 1024)          // +2048
#define BSV_F   (RED_F + 4 * 16 * 34 * 2)   // red = 2176 u64 = 4352 floats
#define SLEN_F  (BSV_F + 64)
#define SMEM_FLOATS (SLEN_F + 64)

// Inner GEMM: N k-steps. w dup'd gate-pairs, operand packed batch-pairs.
// Per k: 2 LDS.128 (w) + 1 LDS.128 (4 batches) + 8 FFMA2 = 16 MACs.
template <int N>
__device__ __forceinline__ void gemm_phase(unsigned long long* acc2,
                                           const float* __restrict__ hxp,
                                           const float* __restrict__ wtp) {
    #pragma unroll 8
    for (int kk = 0; kk < N; ++kk) {
        ulonglong2 w01 = *(const ulonglong2*)(wtp + kk * 128);       // (g0,g0),(g1,g1)
        ulonglong2 w23 = *(const ulonglong2*)(wtp + kk * 128 + 64);  // (g2,g2),(g3,g3)
        ulonglong2 h2  = *(const ulonglong2*)(hxp + kk * 16);        // (b0,b1),(b2,b3)
        fmaf2(acc2[0], w01.x, h2.x); fmaf2(acc2[1], w01.x, h2.y);
        fmaf2(acc2[2], w01.y, h2.x); fmaf2(acc2[3], w01.y, h2.y);
        fmaf2(acc2[4], w23.x, h2.x); fmaf2(acc2[5], w23.x, h2.y);
        fmaf2(acc2[6], w23.y, h2.x); fmaf2(acc2[7], w23.y, h2.y);
    }
}

__device__ __forceinline__ void global_barrier(int tid) {
    __syncthreads();
    if (tid == 0) {
        unsigned s0 = *((volatile unsigned*)&g_bsns);
        __threadfence();
        unsigned a = atomicAdd(&g_bcnt, 1u);
        if (a == NBLK - 1) {
            atomicExch(&g_bcnt, 0u);
            __threadfence();
            atomicExch(&g_bsns, s0 ^ 1u);
        } else {
            while (*((volatile unsigned*)&g_bsns) == s0) {}
        }
        __threadfence();
    }
    __syncthreads();
}

// Duplicated-pair weight slice. Slot layout per k (128 floats = 32 slots of 16B):
//   slot nl      (bytes nl*16)       : (g0,g0,g1,g1) for row-group nl   (slots 0..15)
//   slot 16+nl   (bytes 256+nl*16)   : (g2,g2,g3,g3)                    (slots 16..31)
// -> disjoint coverage of all 32 slots; warp's two w LDS.128 each span one
//    conflict-free 128-B region (quad-broadcast across bgq lanes).
__device__ __forceinline__ void load_w_dup(float* wt, const float* __restrict__ W,
                                           int nc, int tid) {
    for (int idx = tid; idx < 256 * 64; idx += NTHR) {
        int k = idx >> 6, row = idx & 63;
        int nl = row >> 2, g = row & 3;
        int j = g * HH + nc * NB_N + nl;
        float w = W[(size_t)j * 256 + k];
        int slot = (g < 2) ? nl : (16 + nl);
        int base = k * 128 + slot * 4 + (g & 1) * 2;
        wt[base] = w; wt[base + 1] = w;
    }
}

extern "C" __global__ void __launch_bounds__(NTHR, 1)
bilstm_kernel(const float* __restrict__ x,
              const int*   __restrict__ lens,
              const float* __restrict__ Wih_f, const float* __restrict__ Whh_f,
              const float* __restrict__ bih_f, const float* __restrict__ bhh_f,
              const float* __restrict__ Wih_b, const float* __restrict__ Whh_b,
              const float* __restrict__ bih_b, const float* __restrict__ bhh_b,
              float* __restrict__ out)
{
    extern __shared__ float smem[];
    float* wt   = smem + WT_F;              // [256][128] dup weights (Wih then Whh)
    float* xst  = smem + XST_F;             // phase A: 2 x-tiles; phase B: h buffer
    float* xps  = smem + XPS_F;             // 2 x 1024 staged xp
    unsigned long long* redu = (unsigned long long*)(smem + RED_F);  // [4][16][34]
    float* bsv  = smem + BSV_F;             // [64] bih+bhh
    int*   slen = (int*)(smem + SLEN_F);    // [64]
    float* tile = wt;                       // prologue transpose tile [256][65]

    const uint32_t xst_b = smem_u32(xst);
    const uint32_t xps_b = smem_u32(xps);

    const int tid  = threadIdx.x;
    const int dir  = blockIdx.x >> 6;
    const int bgrp = (blockIdx.x >> 4) & 3;
    const int nc   = blockIdx.x & 15;
    const int gid  = blockIdx.x >> 4;

    const float* Wih = dir ? Wih_b : Wih_f;
    const float* Whh = dir ? Whh_b : Whh_f;
    const float* bih = dir ? bih_b : bih_f;
    const float* bhh = dir ? bhh_b : bhh_f;

    // thread maps
    const int kq  = tid >> 6;               // K quarter
    const int r6  = tid & 63;
    const int nl  = r6 >> 2;                // row group (4 gate rows)
    const int bgq = r6 & 3;                 // 4-batch group
    const int nl2 = tid >> 4;               // epilogue hidden dim
    const int bl  = tid & 15;               // epilogue batch
    const int n   = nc * NB_N + nl2;
    const int myb = bgrp * NB_B + bl;
    // red index pieces for epilogue
    const int roff = (bl >> 2) * 2 + ((bl >> 1) & 1);
    const int lane = bl & 1;

    // ---------------- prologue ----------------
    if (tid < BB) slen[tid] = lens[tid];
    __syncthreads();

    // transpose x -> g_xt[dir][t][bgrp][k][16b] (non-dup), blocks stride-64 over t
    {
        const int idx64 = blockIdx.x & 63;
        const int bq  = tid >> 2;
        const int kq4 = tid & 3;
        for (int s = idx64; s < TT; s += 64) {
            int t;
            if (dir == 0) t = s;
            else          t = TT - 1 - ((TT - slen[bq] + s) % TT);
            const float* xrow = x + ((size_t)bq * TT + t) * DD;
            #pragma unroll
            for (int kk = 0; kk < 16; ++kk) {
                int k0 = kq4 * 64 + kk * 4;
                float4 v = *(const float4*)(xrow + k0);
                tile[(k0 + 0) * 65 + bq] = v.x;
                tile[(k0 + 1) * 65 + bq] = v.y;
                tile[(k0 + 2) * 65 + bq] = v.z;
                tile[(k0 + 3) * 65 + bq] = v.w;
            }
            __syncthreads();
            const int k2 = tid;
            #pragma unroll
            for (int bg4 = 0; bg4 < 4; ++bg4) {
                float* dst = &g_xt[dir][s][bg4][k2][0];
                #pragma unroll
                for (int q = 0; q < 4; ++q) {
                    float4 o;
                    o.x = tile[k2 * 65 + bg4 * 16 + q * 4 + 0];
                    o.y = tile[k2 * 65 + bg4 * 16 + q * 4 + 1];
                    o.z = tile[k2 * 65 + bg4 * 16 + q * 4 + 2];
                    o.w = tile[k2 * 65 + bg4 * 16 + q * 4 + 3];
                    *(float4*)(dst + q * 4) = o;
                }
            }
            __syncthreads();
        }
    }

    // zero h buffers; set flags (h(0) ready)
    {
        float* hb = &g_hb[0][0][0][0][0];
        const int total = 2 * 2 * 4 * HH * NB_B;
        for (int i = blockIdx.x * NTHR + tid; i < total; i += NBLK * NTHR) hb[i] = 0.f;
    }
    __syncthreads();
    if (tid == 0) *((volatile int*)&g_flag[gid][nc]) = 1;

    global_barrier(tid);   // transpose + h-zero + flags visible chip-wide

    // ---------------- phase A: xp = x @ Wih^T + bih + bhh ----------------
    load_w_dup(wt, Wih, nc, tid);
    if (tid < 64) {
        int nn = tid >> 2, g = tid & 3;
        int j = g * HH + nc * NB_N + nn;
        bsv[tid] = bih[j] + bhh[j];
    }
    __syncthreads();

    // prime x tiles 0,1 (16 KB each, 4 cpa16/thread)
    #pragma unroll
    for (int tp = 0; tp < 2; ++tp) {
        const char* src = (const char*)&g_xt[dir][tp][bgrp][0][0];
        #pragma unroll
        for (int j = 0; j < 4; ++j) {
            int i = tid + j * NTHR;
            cpa16(xst_b + (uint32_t)(tp * 16384 + i * 16), src + (size_t)i * 16);
        }
        CP_COMMIT();
    }

    for (int t = 0; t < TT; ++t) {
        CP_WAIT(1);
        __syncthreads();

        unsigned long long acc2[8];
        #pragma unroll
        for (int i = 0; i < 8; ++i) acc2[i] = 0ull;

        const float* xbuf = xst + (t & 1) * (DD * NB_B);
        gemm_phase<64>(acc2, xbuf + (kq * 64) * 16 + bgq * 4,
                             wt + (kq * 64) * 128 + nl * 4);

        // publish kq-split partials: redu[kq][nl][g*8 + bgq*2 + bp]
        #pragma unroll
        for (int g = 0; g < 4; ++g)
            #pragma unroll
            for (int bp = 0; bp < 2; ++bp)
                redu[(kq * 16 + nl) * 34 + g * 8 + bgq * 2 + bp] = acc2[g * 2 + bp];
        __syncthreads();

        // commit next tile (or empty group to keep wait semantics)
        if (t + 2 < TT) {
            const char* src = (const char*)&g_xt[dir][t + 2][bgrp][0][0];
            #pragma unroll
            for (int j = 0; j < 4; ++j) {
                int i = tid + j * NTHR;
                cpa16(xst_b + (uint32_t)((t & 1) * 16384 + i * 16), src + (size_t)i * 16);
            }
        }
        CP_COMMIT();

        // reduce + bias -> g_xp  (thread = (nl2, bl))
        {
            float4 o;
            float* op = &o.x;
            #pragma unroll
            for (int g = 0; g < 4; ++g) {
                unsigned long long v =
                    addf2(addf2(redu[( 0 + nl2) * 34 + g * 8 + roff],
                                redu[(16 + nl2) * 34 + g * 8 + roff]),
                          addf2(redu[(32 + nl2) * 34 + g * 8 + roff],
                                redu[(48 + nl2) * 34 + g * 8 + roff]));
                float lo, hi; unpack2(v, lo, hi);
                op[g] = (lane ? hi : lo) + bsv[nl2 * 4 + g];
            }
            *(float4*)&g_xp[dir][bgrp][nc][t][(nl2 * 16 + bl) * 4] = o;
        }
    }

    // ---------------- phase B: recurrence (h @ Whh^T) ----------------
    __syncthreads();
    load_w_dup(wt, Whh, nc, tid);
    __syncthreads();

    // prime xp(0)
    {
        const char* src = (const char*)&g_xp[dir][bgrp][nc][0][0];
        cpa16(xps_b + (uint32_t)(tid * 16), src + (size_t)tid * 16);
        CP_COMMIT();
    }

    const float* hxp = xst + (kq * 64) * 16 + bgq * 4;
    const float* wtp = wt  + (kq * 64) * 128 + nl * 4;
    const int L = slen[myb];
    float cth = 0.f;
    int p = 0;

    for (int s = 0; s < TT; ++s) {
        CP_WAIT(0);             // xp(s) staged (and all older groups retired)
        __syncthreads();

        // wait for h(s) from the 16 blocks of this group
        if (tid < GRPBLK) {
            volatile int* fp = &g_flag[gid][tid];
            while (*fp < s + 1) {}
            __threadfence();
        }
        __syncthreads();

        // fetch h(s) 16 KB in two interleaved 32-row halves
        {
            const char* hsrc = (const char*)&g_hb[dir][p][bgrp][0][0];
            #pragma unroll
            for (int j = 0; j < 2; ++j) {   // half A: row blocks 0,2,4,6
                int id = tid + j * NTHR;
                int i = (id & 127) + ((id >> 7) << 8);
                cpa16(xst_b + (uint32_t)(i * 16), hsrc + (size_t)i * 16);
            }
            CP_COMMIT();
            #pragma unroll
            for (int j = 0; j < 2; ++j) {   // half B: row blocks 1,3,5,7
                int id = tid + j * NTHR;
                int i = 128 + (id & 127) + ((id >> 7) << 8);
                cpa16(xst_b + (uint32_t)(i * 16), hsrc + (size_t)i * 16);
            }
            CP_COMMIT();
        }

        unsigned long long acc2[8];
        #pragma unroll
        for (int i = 0; i < 8; ++i) acc2[i] = 0ull;

        CP_WAIT(1);             // half A landed
        __syncthreads();
        gemm_phase<32>(acc2, hxp, wtp);
        CP_WAIT(0);             // half B landed
        __syncthreads();
        gemm_phase<32>(acc2, hxp + 32 * 16, wtp + 32 * 128);

        // publish kq-split partials
        #pragma unroll
        for (int g = 0; g < 4; ++g)
            #pragma unroll
            for (int bp = 0; bp < 2; ++bp)
                redu[(kq * 16 + nl) * 34 + g * 8 + bgq * 2 + bp] = acc2[g * 2 + bp];
        __syncthreads();

        // prefetch xp(s+1) (overlaps epilogue + flag + skew)
        if (s + 1 < TT) {
            const char* src = (const char*)&g_xp[dir][bgrp][nc][s + 1][0];
            cpa16(xps_b + (uint32_t)(((s + 1) & 1) * 4096 + tid * 16),
                  src + (size_t)tid * 16);
            CP_COMMIT();
        }

        // epilogue: reduce + xp + gates + cell update (1 cell per thread)
        float hval;
        {
            float4 xv = *(float4*)&xps[(s & 1) * 1024 + (nl2 * 16 + bl) * 4];
            float pre[4];
            float* xp4 = &xv.x;
            #pragma unroll
            for (int g = 0; g < 4; ++g) {
                unsigned long long v =
                    addf2(addf2(redu[( 0 + nl2) * 34 + g * 8 + roff],
                                redu[(16 + nl2) * 34 + g * 8 + roff]),
                          addf2(redu[(32 + nl2) * 34 + g * 8 + roff],
                                redu[(48 + nl2) * 34 + g * 8 + roff]));
                float lo, hi; unpack2(v, lo, hi);
                pre[g] = (lane ? hi : lo) + xp4[g];
            }
            float si = fsig(pre[0]), sf = fsig(pre[1]);
            float tg = ftanh(pre[2]), so = fsig(pre[3]);
            cth = sf * cth + si * tg;
            hval = so * ftanh(cth);
            g_hb[dir][p ^ 1][bgrp][n][bl] = hval;
        }

        __syncthreads();
        if (tid == 0) {
            __threadfence();
            *((volatile int*)&g_flag[gid][nc]) = s + 2;
        }

        // masked output write (off critical path)
        if (s < L) {
            const int t = dir ? (L - 1 - s) : s;
            out[((size_t)myb * TT + t) * (2 * HH) + dir * HH + n] = hval;
        }

        p ^= 1;
    }

    // final barrier, then reset flags for the next graph replay
    global_barrier(tid);
    if (tid == 0) *((volatile int*)&g_flag[gid][nc]) = 0;
}

extern "C" void kernel_launch(void* const* d_in, const int* in_sizes, int n_in,
                              void* d_out, int out_size) {
    const float* x     = (const float*)d_in[0];
    const int*   lens  = (const int*)  d_in[1];
    const float* Wih_f = (const float*)d_in[2];
    const float* Whh_f = (const float*)d_in[3];
    const float* bih_f = (const float*)d_in[4];
    const float* bhh_f = (const float*)d_in[5];
    const float* Wih_b = (const float*)d_in[6];
    const float* Whh_b = (const float*)d_in[7];
    const float* bih_b = (const float*)d_in[8];
    const float* bhh_b = (const float*)d_in[9];
    float* out = (float*)d_out;

    // zero the padded/masked region (output beyond input_length must be 0)
    cudaMemsetAsync(out, 0, (size_t)out_size * sizeof(float), 0);

    const size_t smem_bytes = (size_t)SMEM_FLOATS * sizeof(float);
    cudaFuncSetAttribute(bilstm_kernel,
                         cudaFuncAttributeMaxDynamicSharedMemorySize, (int)smem_bytes);

    bilstm_kernel<<<NBLK, NTHR, smem_bytes>>>(x, lens, Wih_f, Whh_f, bih_f, bhh_f,
                                              Wih_b, Whh_b, bih_b, bhh_b, out);
}

// round 11
// speedup vs baseline: 1.2257x; 1.2257x over previous
#include <cuda_runtime.h>
#include <cstdint>
#include <math.h>

#define BB 64
#define TT 512
#define DD 256
#define HH 256
#define KK 512
#define NTHR 256
#define NBLK 128
#define NB_N 16        // hidden dims per block
#define NB_B 16        // batches per block
#define NGRP 8         // sync groups (dir x bgrp)
#define GRPBLK 16      // blocks per sync group

// ---------------- device scratch (static allocation, allowed) ----------------
__device__ float g_xt[2][TT][4][DD][2 * NB_B];  // [dir][t][bgrp][k][b-dup]   (128 MB)
__device__ float g_hb[2][2][4][HH][2 * NB_B];   // [dir][phase][bgrp][n][b-dup] (1 MB)
__device__ int      g_flag[NGRP][GRPBLK][32];   // step flags, one 128B line each
__device__ unsigned g_bcnt, g_bsns;             // global barrier (self-stable)

// ---- fast gate math (|rel err| ~1e-6, saturation-safe) ----
__device__ __forceinline__ float fsig(float v) {
    return __fdividef(1.f, 1.f + __expf(-v));
}
__device__ __forceinline__ float ftanh(float v) {
    return 1.f - __fdividef(2.f, __expf(2.f * v) + 1.f);
}

// ---- packed fp32x2 helpers (sm_100+) ----
__device__ __forceinline__ void fmaf2(unsigned long long& d,
                                      unsigned long long a, unsigned long long b) {
    asm("fma.rn.f32x2 %0, %1, %2, %3;" : "=l"(d) : "l"(a), "l"(b), "l"(d));
}
__device__ __forceinline__ unsigned long long addf2(unsigned long long a,
                                                    unsigned long long b) {
    unsigned long long r;
    asm("add.rn.f32x2 %0, %1, %2;" : "=l"(r) : "l"(a), "l"(b));
    return r;
}
__device__ __forceinline__ void unpack2(unsigned long long v, float& lo, float& hi) {
    asm("mov.b64 {%0, %1}, %2;" : "=f"(lo), "=f"(hi) : "l"(v));
}

// ---- release/acquire flag ops (no full membar on the critical path) ----
__device__ __forceinline__ void st_release(int* p, int v) {
    asm volatile("st.release.gpu.global.b32 [%0], %1;" :: "l"(p), "r"(v) : "memory");
}
__device__ __forceinline__ int ld_acquire(const int* p) {
    int v;
    asm volatile("ld.acquire.gpu.global.b32 %0, [%1];" : "=r"(v) : "l"(p) : "memory");
    return v;
}

// ---- cp.async helpers ----
__device__ __forceinline__ void cpa16(uint32_t dst_smem, const void* src) {
    asm volatile("cp.async.cg.shared.global [%0], [%1], 16;"
                 :: "r"(dst_smem), "l"(src));
}
#define CP_COMMIT() asm volatile("cp.async.commit_group;")
#define CP_WAIT(n)  asm volatile("cp.async.wait_group %0;" :: "n"(n))

__device__ __forceinline__ uint32_t smem_u32(const void* p) {
    uint32_t a;
    asm("{ .reg .u64 t; cvta.to.shared.u64 t, %1; cvt.u32.u64 %0, t; }"
        : "=r"(a) : "l"(p));
    return a;
}

// Inner GEMM: N k-steps. Per k: w2 = 2 gate-pairs (g0,g1),(g2,g3) of this nl;
// hA/hB = 4 batches duplicated. 8 FFMA2 = 16 MACs.
template <int N>
__device__ __forceinline__ void gemm_phase(unsigned long long* acc2,
                                           const float* __restrict__ hxp,
                                           const float* __restrict__ wtp) {
    #pragma unroll 8
    for (int kk = 0; kk < N; ++kk) {
        ulonglong2 w2 = *(const ulonglong2*)(wtp + kk * 64);       // (g0,g1),(g2,g3)
        ulonglong2 hA = *(const ulonglong2*)(hxp + kk * 32);       // (b0,b0),(b1,b1)
        ulonglong2 hB = *(const ulonglong2*)(hxp + kk * 32 + 4);   // (b2,b2),(b3,b3)
        fmaf2(acc2[0], w2.x, hA.x); fmaf2(acc2[1], w2.x, hA.y);
        fmaf2(acc2[2], w2.x, hB.x); fmaf2(acc2[3], w2.x, hB.y);
        fmaf2(acc2[4], w2.y, hA.x); fmaf2(acc2[5], w2.y, hA.y);
        fmaf2(acc2[6], w2.y, hB.x); fmaf2(acc2[7], w2.y, hB.y);
    }
}

__device__ __forceinline__ void global_barrier(int tid) {
    __syncthreads();
    if (tid == 0) {
        unsigned s0 = *((volatile unsigned*)&g_bsns);
        __threadfence();
        unsigned a = atomicAdd(&g_bcnt, 1u);
        if (a == NBLK - 1) {
            atomicExch(&g_bcnt, 0u);
            __threadfence();
            atomicExch(&g_bsns, s0 ^ 1u);
        } else {
            while (*((volatile unsigned*)&g_bsns) == s0) {}
        }
        __threadfence();
    }
    __syncthreads();
}

extern "C" __global__ void __launch_bounds__(NTHR, 1)
bilstm_kernel(const float* __restrict__ x,
              const int*   __restrict__ lens,
              const float* __restrict__ Wih_f, const float* __restrict__ Whh_f,
              const float* __restrict__ bih_f, const float* __restrict__ bhh_f,
              const float* __restrict__ Wih_b, const float* __restrict__ Whh_b,
              const float* __restrict__ bih_b, const float* __restrict__ bhh_b,
              float* __restrict__ out)
{
    extern __shared__ float smem[];
    float* hx  = smem;                          // [512][32]  [x_t ; h] batch-dup
    float* wt  = hx + KK * 32;                  // [512][64]  weight rows (gate pairs)
    unsigned long long* red =
        (unsigned long long*)(wt + KK * 64);    // [4][16][2][16] kq-split partials
    float* bsv  = (float*)(red + 4 * 16 * 2 * 16);  // [64] bih+bhh
    int*   slen = (int*)(bsv + 64);             // [64]
    float* tile = wt;                           // prologue transpose tile [256][65]

    const uint32_t hx_base = smem_u32(hx);

    const int tid  = threadIdx.x;
    const int dir  = blockIdx.x >> 6;
    const int bgrp = (blockIdx.x >> 4) & 3;     // 16-batch group
    const int nc   = blockIdx.x & 15;           // 16-hidden-dim chunk
    const int gid  = blockIdx.x >> 4;           // sync group 0..7

    const float* Wih = dir ? Wih_b : Wih_f;
    const float* Whh = dir ? Whh_b : Whh_f;
    const float* bih = dir ? bih_b : bih_f;
    const float* bhh = dir ? bhh_b : bhh_f;

    // ---------------- prologue ----------------
    if (tid < BB) slen[tid] = lens[tid];
    __syncthreads();

    // x transpose+dup via smem tile (per-dir, blocks idx64 stride 64 over t)
    {
        const int idx64 = blockIdx.x & 63;
        const int bq  = tid >> 2;               // batch 0..63
        const int kq4 = tid & 3;                // k quarter 0..3
        for (int s = idx64; s < TT; s += 64) {
            int t;
            if (dir == 0) t = s;
            else          t = TT - 1 - ((TT - slen[bq] + s) % TT);
            const float* xrow = x + ((size_t)bq * TT + t) * DD;
            #pragma unroll
            for (int kk = 0; kk < 16; ++kk) {
                int k0 = kq4 * 64 + kk * 4;
                float4 v = *(const float4*)(xrow + k0);
                tile[(k0 + 0) * 65 + bq] = v.x;
                tile[(k0 + 1) * 65 + bq] = v.y;
                tile[(k0 + 2) * 65 + bq] = v.z;
                tile[(k0 + 3) * 65 + bq] = v.w;
            }
            __syncthreads();
            // write out duplicated, coalesced
            const int k2 = tid;                 // 0..255
            #pragma unroll
            for (int bg4 = 0; bg4 < 4; ++bg4) {
                float* dst = &g_xt[dir][s][bg4][k2][0];
                #pragma unroll
                for (int blp = 0; blp < 8; ++blp) {
                    float f0 = tile[k2 * 65 + bg4 * 16 + blp * 2 + 0];
                    float f1 = tile[k2 * 65 + bg4 * 16 + blp * 2 + 1];
                    float4 w; w.x = f0; w.y = f0; w.z = f1; w.w = f1;
                    *(float4*)(dst + blp * 4) = w;
                }
            }
            __syncthreads();
        }
    }

    // weight slice: wt[k][r], r = nl*4 + g (gate order i,f,g,o), rows for nc
    for (int idx = tid; idx < KK * 64; idx += NTHR) {
        int k = idx >> 6, r = idx & 63;
        int nl = r >> 2, g = r & 3;
        int j = g * HH + nc * NB_N + nl;
        wt[idx] = (k < DD) ? Wih[(size_t)j * DD + k] : Whh[(size_t)j * HH + (k - DD)];
    }
    if (tid < 64) {
        int nl = tid >> 2, g = tid & 3;
        int j = g * HH + nc * NB_N + nl;
        bsv[tid] = bih[j] + bhh[j];
    }
    // zero all h buffers (cooperative across all blocks)
    {
        float* hb = &g_hb[0][0][0][0][0];
        const int total = 2 * 2 * 4 * HH * 2 * NB_B;
        for (int i = blockIdx.x * NTHR + tid; i < total; i += NBLK * NTHR) hb[i] = 0.f;
    }
    __syncthreads();
    if (tid == 0) st_release(&g_flag[gid][nc][0], 1);   // h(0) ready

    global_barrier(tid);

    // prefetch x(0) -> hx x-half (layouts match: contiguous copy)
    {
        const char* xsrc = (const char*)&g_xt[dir][0][bgrp][0][0];
        #pragma unroll
        for (int j = 0; j < 8; ++j) {
            int i = tid + j * NTHR;             // 0..2047 chunks of 16B
            cpa16(hx_base + (uint32_t)(i * 16), xsrc + (size_t)i * 16);
        }
        CP_COMMIT();
    }

    // ---------------- recurrence ----------------
    // GEMM map: kq = K quarter, nl = local hidden (4 gate rows), bgq = 4 batches
    const int kq  = tid >> 6;
    const int r6  = tid & 63;
    const int nl  = r6 >> 2;
    const int bgq = r6 & 3;
    // epilogue map: one (n, b) cell per thread
    const int nl2 = tid >> 4;
    const int bl  = tid & 15;
    const int n   = nc * NB_N + nl2;
    const int myb = bgrp * NB_B + bl;
    const int L   = slen[myb];

    const float* hxp_x  = hx + (kq * 64) * 32 + bgq * 8;
    const float* wtp_x  = wt + (kq * 64) * 64 + nl * 4;
    const float* hxp_hA = hx + (DD + kq * 64) * 32 + bgq * 8;
    const float* wtp_hA = wt + (DD + kq * 64) * 64 + nl * 4;

    float cth = 0.f;
    int p = 0;

    for (int s = 0; s < TT; ++s) {
        CP_WAIT(0);                 // x(s) landed
        __syncthreads();

        unsigned long long acc2[8];
        #pragma unroll
        for (int i = 0; i < 8; ++i) acc2[i] = 0ull;

        // x-half (K=256): independent of h(s); hides skew + flag latency
        gemm_phase<64>(acc2, hxp_x, wtp_x);

        // wait for h(s) from the 16 blocks of this group
        // (acquire-load; padded flags -> one poller-set per L2 line; backoff on miss)
        if (tid < GRPBLK) {
            const int* fp = &g_flag[gid][tid][0];
            int v = ld_acquire(fp);
            while (v < s + 1) {
                __nanosleep(20);
                v = ld_acquire(fp);
            }
        }
        __syncthreads();

        // fetch h(s) in two k-interleaved commit groups (pipelined with gemm)
        {
            const char* hsrc = (const char*)&g_hb[dir][p][bgrp][0][0];
            const uint32_t hdst = hx_base + (uint32_t)(DD * 32 * 4);
            #pragma unroll
            for (int j = 0; j < 4; ++j) {       // group A: kk with (kk & 32)==0
                int a = tid + j * NTHR;         // 0..1023
                int i = (a & 255) + ((a >> 8) << 9);
                cpa16(hdst + (uint32_t)(i * 16), hsrc + (size_t)i * 16);
            }
            CP_COMMIT();
            #pragma unroll
            for (int j = 0; j < 4; ++j) {       // group B: kk with (kk & 32)==32
                int a = tid + j * NTHR;
                int i = 256 + (a & 255) + ((a >> 8) << 9);
                cpa16(hdst + (uint32_t)(i * 16), hsrc + (size_t)i * 16);
            }
            CP_COMMIT();
        }
        CP_WAIT(1);                 // group A in
        __syncthreads();
        gemm_phase<32>(acc2, hxp_hA, wtp_hA);
        CP_WAIT(0);                 // group B in
        __syncthreads();
        gemm_phase<32>(acc2, hxp_hA + 32 * 32, wtp_hA + 32 * 64);

        // publish kq-split packed partials: red[kq][nl][pr][b16]
        #pragma unroll
        for (int pr = 0; pr < 2; ++pr)
            #pragma unroll
            for (int bi = 0; bi < 4; ++bi)
                red[(((kq * 16 + nl) * 2 + pr) * 16) + bgq * 4 + bi] = acc2[pr * 4 + bi];
        __syncthreads();

        // prefetch x(s+1): overlaps epilogue + flag post + next-step skew
        if (s + 1 < TT) {
            const char* xsrc = (const char*)&g_xt[dir][s + 1][bgrp][0][0];
            #pragma unroll
            for (int j = 0; j < 8; ++j) {
                int i = tid + j * NTHR;
                cpa16(hx_base + (uint32_t)(i * 16), xsrc + (size_t)i * 16);
            }
            CP_COMMIT();
        }

        // epilogue: reduce 4 kq, gates, cell update  (1 cell per thread)
        {
            unsigned long long s01 =
                addf2(addf2(red[((0 * 16 + nl2) * 2 + 0) * 16 + bl],
                            red[((1 * 16 + nl2) * 2 + 0) * 16 + bl]),
                      addf2(red[((2 * 16 + nl2) * 2 + 0) * 16 + bl],
                            red[((3 * 16 + nl2) * 2 + 0) * 16 + bl]));
            unsigned long long s23 =
                addf2(addf2(red[((0 * 16 + nl2) * 2 + 1) * 16 + bl],
                            red[((1 * 16 + nl2) * 2 + 1) * 16 + bl]),
                      addf2(red[((2 * 16 + nl2) * 2 + 1) * 16 + bl],
                            red[((3 * 16 + nl2) * 2 + 1) * 16 + bl]));
            float pi, pf, pg, po;
            unpack2(s01, pi, pf);
            unpack2(s23, pg, po);
            pi += bsv[nl2 * 4 + 0];
            pf += bsv[nl2 * 4 + 1];
            pg += bsv[nl2 * 4 + 2];
            po += bsv[nl2 * 4 + 3];

            float si = fsig(pi), sf = fsig(pf), tg = ftanh(pg), so = fsig(po);
            cth = sf * cth + si * tg;
            float hval = so * ftanh(cth);

            float2 hd; hd.x = hval; hd.y = hval;
            *(float2*)&g_hb[dir][p ^ 1][bgrp][n][bl * 2] = hd;

            __syncthreads();        // all h writes done before the release-store
            if (tid == 0) st_release(&g_flag[gid][nc][0], s + 2);

            if (s < L) {
                const int t = dir ? (L - 1 - s) : s;
                out[((size_t)myb * TT + t) * (2 * HH) + dir * HH + n] = hval;
            }
        }
        p ^= 1;
    }

    // final barrier, then reset flags for the next graph replay
    global_barrier(tid);
    if (tid == 0) *((volatile int*)&g_flag[gid][nc][0]) = 0;
}

extern "C" void kernel_launch(void* const* d_in, const int* in_sizes, int n_in,
                              void* d_out, int out_size) {
    const float* x     = (const float*)d_in[0];
    const int*   lens  = (const int*)  d_in[1];
    const float* Wih_f = (const float*)d_in[2];
    const float* Whh_f = (const float*)d_in[3];
    const float* bih_f = (const float*)d_in[4];
    const float* bhh_f = (const float*)d_in[5];
    const float* Wih_b = (const float*)d_in[6];
    const float* Whh_b = (const float*)d_in[7];
    const float* bih_b = (const float*)d_in[8];
    const float* bhh_b = (const float*)d_in[9];
    float* out = (float*)d_out;

    // zero the padded/masked region (output beyond input_length must be 0)
    cudaMemsetAsync(out, 0, (size_t)out_size * sizeof(float), 0);

    const size_t smem_bytes =
        (size_t)(KK * 32 + KK * 64) * sizeof(float)        // hx + wt
        + (size_t)(4 * 16 * 2 * 16) * sizeof(unsigned long long)  // red
        + 64 * sizeof(float) + 64 * sizeof(int);           // bsv + slen
    cudaFuncSetAttribute(bilstm_kernel,
                         cudaFuncAttributeMaxDynamicSharedMemorySize, (int)smem_bytes);

    bilstm_kernel<<<NBLK, NTHR, smem_bytes>>>(x, lens, Wih_f, Whh_f, bih_f, bhh_f,
                                              Wih_b, Whh_b, bih_b, bhh_b, out);
}

// round 13
// speedup vs baseline: 1.7052x; 1.3911x over previous
#include <cuda_runtime.h>
#include <cstdint>
#include <math.h>

#define BB 64
#define TT 512
#define DD 256
#define HH 256
#define KK 512
#define NTHR 256
#define NBLK 128
#define NB_N 16        // hidden dims per block
#define NB_B 16        // batches per block
#define NGRP 8         // sync groups (dir x bgrp)
#define GRPBLK 16      // blocks per sync group

// ---------------- device scratch (static allocation, allowed) ----------------
__device__ float g_xt[2][TT][4][DD][2 * NB_B];  // [dir][t][bgrp][k][b-dup]   (128 MB)
__device__ float g_hb[2][2][4][HH][2 * NB_B];   // [dir][phase][bgrp][n][b-dup] (1 MB)
__device__ int      g_flag[NGRP][GRPBLK][32];   // step flags, one 128B line each
__device__ unsigned g_bcnt, g_bsns;             // global barrier (self-stable)

// ---- fast gate math (|rel err| ~1e-6, saturation-safe) ----
__device__ __forceinline__ float fsig(float v) {
    return __fdividef(1.f, 1.f + __expf(-v));
}
__device__ __forceinline__ float ftanh(float v) {
    return 1.f - __fdividef(2.f, __expf(2.f * v) + 1.f);
}

// ---- packed fp32x2 helpers (sm_100+) ----
__device__ __forceinline__ void fmaf2(unsigned long long& d,
                                      unsigned long long a, unsigned long long b) {
    asm("fma.rn.f32x2 %0, %1, %2, %3;" : "=l"(d) : "l"(a), "l"(b), "l"(d));
}
__device__ __forceinline__ unsigned long long addf2(unsigned long long a,
                                                    unsigned long long b) {
    unsigned long long r;
    asm("add.rn.f32x2 %0, %1, %2;" : "=l"(r) : "l"(a), "l"(b));
    return r;
}
__device__ __forceinline__ void unpack2(unsigned long long v, float& lo, float& hi) {
    asm("mov.b64 {%0, %1}, %2;" : "=f"(lo), "=f"(hi) : "l"(v));
}

// ---- release/acquire flag ops ----
__device__ __forceinline__ void st_release(int* p, int v) {
    asm volatile("st.release.gpu.global.b32 [%0], %1;" :: "l"(p), "r"(v) : "memory");
}
__device__ __forceinline__ int ld_acquire(const int* p) {
    int v;
    asm volatile("ld.acquire.gpu.global.b32 %0, [%1];" : "=r"(v) : "l"(p) : "memory");
    return v;
}

// ---- mbarrier + bulk-copy helpers (single-instruction 32KB transfers) ----
#define MBAR_INIT(addr, cnt) \
    asm volatile("mbarrier.init.shared.b64 [%0], %1;" :: "r"(addr), "r"(cnt) : "memory")
#define MBAR_EXPECT(addr, bytes) \
    asm volatile("mbarrier.arrive.expect_tx.shared.b64 _, [%0], %1;" \
                 :: "r"(addr), "r"(bytes) : "memory")
__device__ __forceinline__ void mbar_wait(uint32_t addr, uint32_t parity) {
    uint32_t done;
    asm volatile(
        "{\n\t.reg .pred p;\n\t"
        "mbarrier.try_wait.parity.shared.b64 p, [%1], %2;\n\t"
        "selp.b32 %0, 1, 0, p;\n\t}"
        : "=r"(done) : "r"(addr), "r"(parity) : "memory");
    while (!done) {
        asm volatile(
            "{\n\t.reg .pred p;\n\t"
            "mbarrier.try_wait.parity.shared.b64 p, [%1], %2, 0x989680;\n\t"
            "selp.b32 %0, 1, 0, p;\n\t}"
            : "=r"(done) : "r"(addr), "r"(parity) : "memory");
    }
}
__device__ __forceinline__ void bulk_g2s(uint32_t dst, const void* src,
                                         uint32_t bytes, uint32_t mbar) {
    asm volatile(
        "cp.async.bulk.shared::cta.global.mbarrier::complete_tx::bytes "
        "[%0], [%1], %2, [%3];"
        :: "r"(dst), "l"(src), "r"(bytes), "r"(mbar) : "memory");
}

__device__ __forceinline__ uint32_t smem_u32(const void* p) {
    uint32_t a;
    asm("{ .reg .u64 t; cvta.to.shared.u64 t, %1; cvt.u32.u64 %0, t; }"
        : "=r"(a) : "l"(p));
    return a;
}

__device__ __forceinline__ void global_barrier(int tid) {
    __syncthreads();
    if (tid == 0) {
        unsigned s0 = *((volatile unsigned*)&g_bsns);
        __threadfence();
        unsigned a = atomicAdd(&g_bcnt, 1u);
        if (a == NBLK - 1) {
            atomicExch(&g_bcnt, 0u);
            __threadfence();
            atomicExch(&g_bsns, s0 ^ 1u);
        } else {
            while (*((volatile unsigned*)&g_bsns) == s0) {}
        }
        __threadfence();
    }
    __syncthreads();
}

// SMEM float offsets
#define WT_F    0                       // [512][64]   128 KB (prologue tile aliases)
#define HX_F    (KK * 64)               // [512][32]   64 KB  ([x ; h] dup'd operand)
#define RED_F   (HX_F + KK * 32)        // u64[8][16][2][16] = 32 KB
#define BSV_F   (RED_F + 8192)          // [64]
#define SLEN_F  (BSV_F + 64)            // [64]
#define MB_F    (SLEN_F + 64)           // 2 x u64 mbarriers
#define SMEM_FLOATS (MB_F + 4)

// Inner GEMM: N k-steps, thread tile = 2 row-groups x 4 gates x 4 batches.
// Per k: 4 LDS.128 (w row nl, w row nl+8, hA, hB) + 16 FFMA2 = 32 MACs.
template <int N>
__device__ __forceinline__ void gemm_phase(unsigned long long* acc,
                                           const float* __restrict__ hp,
                                           const float* __restrict__ wp) {
    #pragma unroll 8
    for (int kk = 0; kk < N; ++kk) {
        ulonglong2 w1 = *(const ulonglong2*)(wp + kk * 64);        // row nl:   (i,f),(g,o)
        ulonglong2 w2 = *(const ulonglong2*)(wp + kk * 64 + 32);   // row nl+8: (i,f),(g,o)
        ulonglong2 hA = *(const ulonglong2*)(hp + kk * 32);        // (b0,b0),(b1,b1)
        ulonglong2 hB = *(const ulonglong2*)(hp + kk * 32 + 4);    // (b2,b2),(b3,b3)
        fmaf2(acc[0],  w1.x, hA.x); fmaf2(acc[1],  w1.x, hA.y);
        fmaf2(acc[2],  w1.x, hB.x); fmaf2(acc[3],  w1.x, hB.y);
        fmaf2(acc[4],  w1.y, hA.x); fmaf2(acc[5],  w1.y, hA.y);
        fmaf2(acc[6],  w1.y, hB.x); fmaf2(acc[7],  w1.y, hB.y);
        fmaf2(acc[8],  w2.x, hA.x); fmaf2(acc[9],  w2.x, hA.y);
        fmaf2(acc[10], w2.x, hB.x); fmaf2(acc[11], w2.x, hB.y);
        fmaf2(acc[12], w2.y, hA.x); fmaf2(acc[13], w2.y, hA.y);
        fmaf2(acc[14], w2.y, hB.x); fmaf2(acc[15], w2.y, hB.y);
    }
}

extern "C" __global__ void __launch_bounds__(NTHR, 1)
bilstm_kernel(const float* __restrict__ x,
              const int*   __restrict__ lens,
              const float* __restrict__ Wih_f, const float* __restrict__ Whh_f,
              const float* __restrict__ bih_f, const float* __restrict__ bhh_f,
              const float* __restrict__ Wih_b, const float* __restrict__ Whh_b,
              const float* __restrict__ bih_b, const float* __restrict__ bhh_b,
              float* __restrict__ out)
{
    extern __shared__ float smem[];
    float* wt = smem + WT_F;                // [512][64] weight rows, r = nl*4+g
    float* hx = smem + HX_F;                // [512][32] staged [x ; h], batch-dup
    unsigned long long* red = (unsigned long long*)(smem + RED_F);
    float* bsv  = smem + BSV_F;
    int*   slen = (int*)(smem + SLEN_F);
    float* tile = wt;                       // prologue transpose tile [256][65]

    const uint32_t hx_b  = smem_u32(hx);
    const uint32_t mbx_b = smem_u32(smem + MB_F);       // x-tile mbarrier
    const uint32_t mbh_b = mbx_b + 8;                   // h-tile mbarrier

    const int tid  = threadIdx.x;
    const int dir  = blockIdx.x >> 6;
    const int bgrp = (blockIdx.x >> 4) & 3;
    const int nc   = blockIdx.x & 15;
    const int gid  = blockIdx.x >> 4;

    const float* Wih = dir ? Wih_b : Wih_f;
    const float* Whh = dir ? Whh_b : Whh_f;
    const float* bih = dir ? bih_b : bih_f;
    const float* bhh = dir ? bhh_b : bhh_f;

    // ---------------- prologue ----------------
    if (tid < BB) slen[tid] = lens[tid];
    __syncthreads();

    // x transpose+dup via smem tile (per-dir, blocks idx64 stride 64 over t)
    {
        const int idx64 = blockIdx.x & 63;
        const int bq  = tid >> 2;
        const int kq4 = tid & 3;
        for (int s = idx64; s < TT; s += 64) {
            int t;
            if (dir == 0) t = s;
            else          t = TT - 1 - ((TT - slen[bq] + s) % TT);
            const float* xrow = x + ((size_t)bq * TT + t) * DD;
            #pragma unroll
            for (int kk = 0; kk < 16; ++kk) {
                int k0 = kq4 * 64 + kk * 4;
                float4 v = *(const float4*)(xrow + k0);
                tile[(k0 + 0) * 65 + bq] = v.x;
                tile[(k0 + 1) * 65 + bq] = v.y;
                tile[(k0 + 2) * 65 + bq] = v.z;
                tile[(k0 + 3) * 65 + bq] = v.w;
            }
            __syncthreads();
            const int k2 = tid;
            #pragma unroll
            for (int bg4 = 0; bg4 < 4; ++bg4) {
                float* dst = &g_xt[dir][s][bg4][k2][0];
                #pragma unroll
                for (int blp = 0; blp < 8; ++blp) {
                    float f0 = tile[k2 * 65 + bg4 * 16 + blp * 2 + 0];
                    float f1 = tile[k2 * 65 + bg4 * 16 + blp * 2 + 1];
                    float4 w; w.x = f0; w.y = f0; w.z = f1; w.w = f1;
                    *(float4*)(dst + blp * 4) = w;
                }
            }
            __syncthreads();
        }
    }

    // weight slice: wt[k][r], r = nl*4 + g (gate order i,f,g,o)
    for (int idx = tid; idx < KK * 64; idx += NTHR) {
        int k = idx >> 6, r = idx & 63;
        int nl = r >> 2, g = r & 3;
        int j = g * HH + nc * NB_N + nl;
        wt[idx] = (k < DD) ? Wih[(size_t)j * DD + k] : Whh[(size_t)j * HH + (k - DD)];
    }
    if (tid < 64) {
        int nl = tid >> 2, g = tid & 3;
        int j = g * HH + nc * NB_N + nl;
        bsv[tid] = bih[j] + bhh[j];
    }
    // zero all h buffers (cooperative across all blocks)
    {
        float* hb = &g_hb[0][0][0][0][0];
        const int total = 2 * 2 * 4 * HH * 2 * NB_B;
        for (int i = blockIdx.x * NTHR + tid; i < total; i += NBLK * NTHR) hb[i] = 0.f;
    }
    if (tid == 0) {
        MBAR_INIT(mbx_b, 1);
        MBAR_INIT(mbh_b, 1);
    }
    __syncthreads();
    if (tid == 0) st_release(&g_flag[gid][nc][0], 1);   // h(0) ready

    global_barrier(tid);

    // prime x(0): single bulk copy, 32 KB
    if (tid == 0) {
        MBAR_EXPECT(mbx_b, 32768u);
        bulk_g2s(hx_b, &g_xt[dir][0][bgrp][0][0], 32768u, mbx_b);
    }

    // ---------------- recurrence ----------------
    // gemm map: warp = k-group (kq8 = 0..7, 32 k each half); lane -> (nl, bgq)
    const int kq8 = tid >> 5;
    const int lane = tid & 31;
    const int nl  = lane >> 2;
    const int bgq = lane & 3;
    // epilogue map: one (n, b) cell per thread
    const int nl2 = tid >> 4;
    const int bl  = tid & 15;
    const int n   = nc * NB_N + nl2;
    const int myb = bgrp * NB_B + bl;
    const int L   = slen[myb];

    const float* wp_x = wt + (kq8 * 32) * 64 + nl * 4;
    const float* hp_x = hx + (kq8 * 32) * 32 + bgq * 8;
    const float* wp_h = wt + (DD + kq8 * 32) * 64 + nl * 4;
    const float* hp_h = hx + (DD + kq8 * 32) * 32 + bgq * 8;

    float cth = 0.f;
    int p = 0;

    for (int s = 0; s < TT; ++s) {
        const uint32_t ph = (uint32_t)(s & 1);

        mbar_wait(mbx_b, ph);               // x(s) landed (every thread waits)

        unsigned long long acc[16];
        #pragma unroll
        for (int i = 0; i < 16; ++i) acc[i] = 0ull;

        // x-half: independent of h(s); hides skew + flag latency
        gemm_phase<32>(acc, hp_x, wp_x);

        // wait for h(s) from the 16 blocks of this group
        if (tid < GRPBLK) {
            const int* fp = &g_flag[gid][tid][0];
            int v = ld_acquire(fp);
            while (v < s + 1) {
                __nanosleep(20);
                v = ld_acquire(fp);
            }
        }
        __syncthreads();

        // fetch h(s): single 32 KB bulk copy (256 rows x 32 floats, batch-dup)
        if (tid == 0) {
            MBAR_EXPECT(mbh_b, 32768u);
            bulk_g2s(hx_b + (uint32_t)(DD * 32 * 4),
                     &g_hb[dir][p][bgrp][0][0], 32768u, mbh_b);
        }
        mbar_wait(mbh_b, ph);

        // h-half
        gemm_phase<32>(acc, hp_h, wp_h);

        // publish k-split partials: red[kq8][row][pr][b16] as u64-pair stores
        #pragma unroll
        for (int rg = 0; rg < 2; ++rg)
            #pragma unroll
            for (int pr = 0; pr < 2; ++pr)
                #pragma unroll
                for (int bp = 0; bp < 2; ++bp) {
                    int row = nl + rg * 8;
                    ulonglong2 v;
                    v.x = acc[rg * 8 + pr * 4 + bp * 2 + 0];
                    v.y = acc[rg * 8 + pr * 4 + bp * 2 + 1];
                    *(ulonglong2*)&red[(((kq8 * 16 + row) * 2 + pr) * 16)
                                       + bgq * 4 + bp * 2] = v;
                }
        __syncthreads();   // all warps done with gemm + x region of hx

        // prefetch x(s+1): one bulk; overlaps epilogue + flag post + skew
        if (s + 1 < TT && tid == 0) {
            MBAR_EXPECT(mbx_b, 32768u);
            bulk_g2s(hx_b, &g_xt[dir][s + 1][bgrp][0][0], 32768u, mbx_b);
        }

        // epilogue: reduce 8 k-groups, gates, cell update (1 cell per thread)
        {
            unsigned long long s01 = 0ull, s23 = 0ull;
            #pragma unroll
            for (int q = 0; q < 8; ++q) {
                s01 = addf2(s01, red[((q * 16 + nl2) * 2 + 0) * 16 + bl]);
                s23 = addf2(s23, red[((q * 16 + nl2) * 2 + 1) * 16 + bl]);
            }
            float pi, pf, pg, po;
            unpack2(s01, pi, pf);
            unpack2(s23, pg, po);
            pi += bsv[nl2 * 4 + 0];
            pf += bsv[nl2 * 4 + 1];
            pg += bsv[nl2 * 4 + 2];
            po += bsv[nl2 * 4 + 3];

            float si = fsig(pi), sf = fsig(pf), tg = ftanh(pg), so = fsig(po);
            cth = sf * cth + si * tg;
            float hval = so * ftanh(cth);

            float2 hd; hd.x = hval; hd.y = hval;
            *(float2*)&g_hb[dir][p ^ 1][bgrp][n][bl * 2] = hd;

            __syncthreads();        // all h writes done before the release-store
            if (tid == 0) st_release(&g_flag[gid][nc][0], s + 2);

            if (s < L) {
                const int t = dir ? (L - 1 - s) : s;
                out[((size_t)myb * TT + t) * (2 * HH) + dir * HH + n] = hval;
            }
        }
        p ^= 1;
    }

    // final barrier, then reset flags for the next graph replay
    global_barrier(tid);
    if (tid == 0) *((volatile int*)&g_flag[gid][nc][0]) = 0;
}

extern "C" void kernel_launch(void* const* d_in, const int* in_sizes, int n_in,
                              void* d_out, int out_size) {
    const float* x     = (const float*)d_in[0];
    const int*   lens  = (const int*)  d_in[1];
    const float* Wih_f = (const float*)d_in[2];
    const float* Whh_f = (const float*)d_in[3];
    const float* bih_f = (const float*)d_in[4];
    const float* bhh_f = (const float*)d_in[5];
    const float* Wih_b = (const float*)d_in[6];
    const float* Whh_b = (const float*)d_in[7];
    const float* bih_b = (const float*)d_in[8];
    const float* bhh_b = (const float*)d_in[9];
    float* out = (float*)d_out;

    // zero the padded/masked region (output beyond input_length must be 0)
    cudaMemsetAsync(out, 0, (size_t)out_size * sizeof(float), 0);

    const size_t smem_bytes = (size_t)SMEM_FLOATS * sizeof(float);
    cudaFuncSetAttribute(bilstm_kernel,
                         cudaFuncAttributeMaxDynamicSharedMemorySize, (int)smem_bytes);

    bilstm_kernel<<<NBLK, NTHR, smem_bytes>>>(x, lens, Wih_f, Whh_f, bih_f, bhh_f,
                                              Wih_b, Whh_b, bih_b, bhh_b, out);
}

// round 14
// speedup vs baseline: 1.9211x; 1.1266x over previous
#include <cuda_runtime.h>
#include <cstdint>
#include <math.h>

#define BB 64
#define TT 512
#define DD 256
#define HH 256
#define KK 512
#define NTHR 256
#define NBLK 128
#define NB_N 16        // hidden dims per block
#define NB_B 16        // batches per block
#define NGRP 8         // sync groups (dir x bgrp)
#define GRPBLK 16      // blocks per sync group

// ---------------- device scratch (static allocation, allowed) ----------------
__device__ float g_xt[2][TT][4][DD][2 * NB_B];  // [dir][t][bgrp][k][b-dup]   (128 MB)
__device__ float g_hb[2][2][4][HH][2 * NB_B];   // [dir][phase][bgrp][n][b-dup] (1 MB)
__device__ int      g_flag[NGRP][GRPBLK][32];   // step flags, one 128B line each
__device__ unsigned g_bcnt, g_bsns;             // global barrier (self-stable)

// ---- fast gate math (|rel err| ~1e-6, saturation-safe) ----
__device__ __forceinline__ float fsig(float v) {
    return __fdividef(1.f, 1.f + __expf(-v));
}
__device__ __forceinline__ float ftanh(float v) {
    return 1.f - __fdividef(2.f, __expf(2.f * v) + 1.f);
}

// ---- packed fp32x2 helpers (sm_100+) ----
__device__ __forceinline__ void fmaf2(unsigned long long& d,
                                      unsigned long long a, unsigned long long b) {
    asm("fma.rn.f32x2 %0, %1, %2, %3;" : "=l"(d) : "l"(a), "l"(b), "l"(d));
}
__device__ __forceinline__ unsigned long long addf2(unsigned long long a,
                                                    unsigned long long b) {
    unsigned long long r;
    asm("add.rn.f32x2 %0, %1, %2;" : "=l"(r) : "l"(a), "l"(b));
    return r;
}
__device__ __forceinline__ void unpack2(unsigned long long v, float& lo, float& hi) {
    asm("mov.b64 {%0, %1}, %2;" : "=f"(lo), "=f"(hi) : "l"(v));
}

// ---- release/acquire flag ops ----
__device__ __forceinline__ void st_release(int* p, int v) {
    asm volatile("st.release.gpu.global.b32 [%0], %1;" :: "l"(p), "r"(v) : "memory");
}
__device__ __forceinline__ int ld_acquire(const int* p) {
    int v;
    asm volatile("ld.acquire.gpu.global.b32 %0, [%1];" : "=r"(v) : "l"(p) : "memory");
    return v;
}

// ---- mbarrier + bulk-copy helpers (single-instruction 32KB transfers) ----
#define MBAR_INIT(addr, cnt) \
    asm volatile("mbarrier.init.shared.b64 [%0], %1;" :: "r"(addr), "r"(cnt) : "memory")
#define MBAR_EXPECT(addr, bytes) \
    asm volatile("mbarrier.arrive.expect_tx.shared.b64 _, [%0], %1;" \
                 :: "r"(addr), "r"(bytes) : "memory")
__device__ __forceinline__ void mbar_wait(uint32_t addr, uint32_t parity) {
    uint32_t done;
    asm volatile(
        "{\n\t.reg .pred p;\n\t"
        "mbarrier.try_wait.parity.shared.b64 p, [%1], %2;\n\t"
        "selp.b32 %0, 1, 0, p;\n\t}"
        : "=r"(done) : "r"(addr), "r"(parity) : "memory");
    while (!done) {
        asm volatile(
            "{\n\t.reg .pred p;\n\t"
            "mbarrier.try_wait.parity.shared.b64 p, [%1], %2, 0x989680;\n\t"
            "selp.b32 %0, 1, 0, p;\n\t}"
            : "=r"(done) : "r"(addr), "r"(parity) : "memory");
    }
}
__device__ __forceinline__ void bulk_g2s(uint32_t dst, const void* src,
                                         uint32_t bytes, uint32_t mbar) {
    asm volatile(
        "cp.async.bulk.shared::cta.global.mbarrier::complete_tx::bytes "
        "[%0], [%1], %2, [%3];"
        :: "r"(dst), "l"(src), "r"(bytes), "r"(mbar) : "memory");
}

__device__ __forceinline__ uint32_t smem_u32(const void* p) {
    uint32_t a;
    asm("{ .reg .u64 t; cvta.to.shared.u64 t, %1; cvt.u32.u64 %0, t; }"
        : "=r"(a) : "l"(p));
    return a;
}

__device__ __forceinline__ void global_barrier(int tid) {
    __syncthreads();
    if (tid == 0) {
        unsigned s0 = *((volatile unsigned*)&g_bsns);
        __threadfence();
        unsigned a = atomicAdd(&g_bcnt, 1u);
        if (a == NBLK - 1) {
            atomicExch(&g_bcnt, 0u);
            __threadfence();
            atomicExch(&g_bsns, s0 ^ 1u);
        } else {
            while (*((volatile unsigned*)&g_bsns) == s0) {}
        }
        __threadfence();
    }
    __syncthreads();
}

// SMEM float offsets
#define WT_F    0                       // [512][64]   128 KB (prologue tile aliases)
#define HX_F    (KK * 64)               // [512][32]   64 KB  ([x ; h] dup'd operand)
#define RED_F   (HX_F + KK * 32)        // u64[8][16][2][16] = 32 KB
#define BSV_F   (RED_F + 8192)          // [64]
#define SLEN_F  (BSV_F + 64)            // [64]
#define MB_F    (SLEN_F + 64)           // 2 x u64 mbarriers
#define SMEM_FLOATS (MB_F + 4)

// Inner GEMM: N k-steps, thread tile = 2 row-groups x 4 gates x 4 batches.
// Per k: 4 LDS.128 (w row nl, w row nl+8, hA, hB) + 16 FFMA2 = 32 MACs.
template <int N>
__device__ __forceinline__ void gemm_phase(unsigned long long* acc,
                                           const float* __restrict__ hp,
                                           const float* __restrict__ wp) {
    #pragma unroll 8
    for (int kk = 0; kk < N; ++kk) {
        ulonglong2 w1 = *(const ulonglong2*)(wp + kk * 64);        // row nl:   (i,f),(g,o)
        ulonglong2 w2 = *(const ulonglong2*)(wp + kk * 64 + 32);   // row nl+8: (i,f),(g,o)
        ulonglong2 hA = *(const ulonglong2*)(hp + kk * 32);        // (b0,b0),(b1,b1)
        ulonglong2 hB = *(const ulonglong2*)(hp + kk * 32 + 4);    // (b2,b2),(b3,b3)
        fmaf2(acc[0],  w1.x, hA.x); fmaf2(acc[1],  w1.x, hA.y);
        fmaf2(acc[2],  w1.x, hB.x); fmaf2(acc[3],  w1.x, hB.y);
        fmaf2(acc[4],  w1.y, hA.x); fmaf2(acc[5],  w1.y, hA.y);
        fmaf2(acc[6],  w1.y, hB.x); fmaf2(acc[7],  w1.y, hB.y);
        fmaf2(acc[8],  w2.x, hA.x); fmaf2(acc[9],  w2.x, hA.y);
        fmaf2(acc[10], w2.x, hB.x); fmaf2(acc[11], w2.x, hB.y);
        fmaf2(acc[12], w2.y, hA.x); fmaf2(acc[13], w2.y, hA.y);
        fmaf2(acc[14], w2.y, hB.x); fmaf2(acc[15], w2.y, hB.y);
    }
}

extern "C" __global__ void __launch_bounds__(NTHR, 1)
bilstm_kernel(const float* __restrict__ x,
              const int*   __restrict__ lens,
              const float* __restrict__ Wih_f, const float* __restrict__ Whh_f,
              const float* __restrict__ bih_f, const float* __restrict__ bhh_f,
              const float* __restrict__ Wih_b, const float* __restrict__ Whh_b,
              const float* __restrict__ bih_b, const float* __restrict__ bhh_b,
              float* __restrict__ out)
{
    extern __shared__ float smem[];
    float* wt = smem + WT_F;                // [512][64] weight rows, r = nl*4+g
    float* hx = smem + HX_F;                // [512][32] staged [x ; h], batch-dup
    unsigned long long* red = (unsigned long long*)(smem + RED_F);
    float* bsv  = smem + BSV_F;
    int*   slen = (int*)(smem + SLEN_F);
    float* tile = wt;                       // prologue transpose tile [256][65]

    const uint32_t hx_b  = smem_u32(hx);
    const uint32_t mbx_b = smem_u32(smem + MB_F);       // x-tile mbarrier
    const uint32_t mbh_b = mbx_b + 8;                   // h-tile mbarrier

    const int tid  = threadIdx.x;
    const int dir  = blockIdx.x >> 6;
    const int bgrp = (blockIdx.x >> 4) & 3;
    const int nc   = blockIdx.x & 15;
    const int gid  = blockIdx.x >> 4;

    const float* Wih = dir ? Wih_b : Wih_f;
    const float* Whh = dir ? Whh_b : Whh_f;
    const float* bih = dir ? bih_b : bih_f;
    const float* bhh = dir ? bhh_b : bhh_f;

    // ---------------- prologue ----------------
    if (tid < BB) slen[tid] = lens[tid];
    __syncthreads();

    // x transpose+dup via smem tile (per-dir, blocks idx64 stride 64 over t)
    {
        const int idx64 = blockIdx.x & 63;
        const int bq  = tid >> 2;
        const int kq4 = tid & 3;
        for (int s = idx64; s < TT; s += 64) {
            int t;
            if (dir == 0) t = s;
            else          t = TT - 1 - ((TT - slen[bq] + s) % TT);
            const float* xrow = x + ((size_t)bq * TT + t) * DD;
            #pragma unroll
            for (int kk = 0; kk < 16; ++kk) {
                int k0 = kq4 * 64 + kk * 4;
                float4 v = *(const float4*)(xrow + k0);
                tile[(k0 + 0) * 65 + bq] = v.x;
                tile[(k0 + 1) * 65 + bq] = v.y;
                tile[(k0 + 2) * 65 + bq] = v.z;
                tile[(k0 + 3) * 65 + bq] = v.w;
            }
            __syncthreads();
            const int k2 = tid;
            #pragma unroll
            for (int bg4 = 0; bg4 < 4; ++bg4) {
                float* dst = &g_xt[dir][s][bg4][k2][0];
                #pragma unroll
                for (int blp = 0; blp < 8; ++blp) {
                    float f0 = tile[k2 * 65 + bg4 * 16 + blp * 2 + 0];
                    float f1 = tile[k2 * 65 + bg4 * 16 + blp * 2 + 1];
                    float4 w; w.x = f0; w.y = f0; w.z = f1; w.w = f1;
                    *(float4*)(dst + blp * 4) = w;
                }
            }
            __syncthreads();
        }
    }

    // weight slice: wt[k][r], r = nl*4 + g (gate order i,f,g,o)
    for (int idx = tid; idx < KK * 64; idx += NTHR) {
        int k = idx >> 6, r = idx & 63;
        int nl = r >> 2, g = r & 3;
        int j = g * HH + nc * NB_N + nl;
        wt[idx] = (k < DD) ? Wih[(size_t)j * DD + k] : Whh[(size_t)j * HH + (k - DD)];
    }
    if (tid < 64) {
        int nl = tid >> 2, g = tid & 3;
        int j = g * HH + nc * NB_N + nl;
        bsv[tid] = bih[j] + bhh[j];
    }
    // zero all h buffers (cooperative across all blocks)
    {
        float* hb = &g_hb[0][0][0][0][0];
        const int total = 2 * 2 * 4 * HH * 2 * NB_B;
        for (int i = blockIdx.x * NTHR + tid; i < total; i += NBLK * NTHR) hb[i] = 0.f;
    }
    if (tid == 0) {
        MBAR_INIT(mbx_b, 1);
        MBAR_INIT(mbh_b, 1);
    }
    __syncthreads();
    if (tid == 0) st_release(&g_flag[gid][nc][0], 1);   // h(0) ready

    global_barrier(tid);

    // prime x(0): single bulk copy, 32 KB
    if (tid == 0) {
        MBAR_EXPECT(mbx_b, 32768u);
        bulk_g2s(hx_b, &g_xt[dir][0][bgrp][0][0], 32768u, mbx_b);
    }

    // ---------------- recurrence ----------------
    // gemm map: warp = k-group (kq8 = 0..7, 32 k each half); lane -> (nl, bgq)
    const int kq8 = tid >> 5;
    const int lane = tid & 31;
    const int nl  = lane >> 2;
    const int bgq = lane & 3;
    // epilogue map: one (n, b) cell per thread
    const int nl2 = tid >> 4;
    const int bl  = tid & 15;
    const int n   = nc * NB_N + nl2;
    const int myb = bgrp * NB_B + bl;
    const int L   = slen[myb];

    const float* wp_x = wt + (kq8 * 32) * 64 + nl * 4;
    const float* hp_x = hx + (kq8 * 32) * 32 + bgq * 8;
    const float* wp_h = wt + (DD + kq8 * 32) * 64 + nl * 4;
    const float* hp_h = hx + (DD + kq8 * 32) * 32 + bgq * 8;

    float cth = 0.f;
    int p = 0;

    for (int s = 0; s < TT; ++s) {
        const uint32_t ph = (uint32_t)(s & 1);

        // warp 7: producer role. Poll peer flags + issue h(s) bulk FIRST, so the
        // transfer overlaps everyone's x-gemm. Safe: all warps finished the
        // previous h-gemm before step s-1's publish-__syncthreads, so the hx
        // h-region is free to overwrite.
        if (kq8 == 7) {
            if (lane < GRPBLK) {
                const int* fp = &g_flag[gid][lane][0];
                int v = ld_acquire(fp);
                while (v < s + 1) {
                    __nanosleep(20);
                    v = ld_acquire(fp);
                }
            }
            __syncwarp();
            if (lane == 0) {
                MBAR_EXPECT(mbh_b, 32768u);
                bulk_g2s(hx_b + (uint32_t)(DD * 32 * 4),
                         &g_hb[dir][p][bgrp][0][0], 32768u, mbh_b);
            }
        }

        mbar_wait(mbx_b, ph);               // x(s) landed

        unsigned long long acc[16];
        #pragma unroll
        for (int i = 0; i < 16; ++i) acc[i] = 0ull;

        // x-half: overlaps the in-flight h bulk + peer skew
        gemm_phase<32>(acc, hp_x, wp_x);

        // h(s) should already be resident; near-zero wait
        mbar_wait(mbh_b, ph);

        // h-half
        gemm_phase<32>(acc, hp_h, wp_h);

        // publish k-split partials: red[kq8][row][pr][b16] as u64-pair stores
        #pragma unroll
        for (int rg = 0; rg < 2; ++rg)
            #pragma unroll
            for (int pr = 0; pr < 2; ++pr)
                #pragma unroll
                for (int bp = 0; bp < 2; ++bp) {
                    int row = nl + rg * 8;
                    ulonglong2 v;
                    v.x = acc[rg * 8 + pr * 4 + bp * 2 + 0];
                    v.y = acc[rg * 8 + pr * 4 + bp * 2 + 1];
                    *(ulonglong2*)&red[(((kq8 * 16 + row) * 2 + pr) * 16)
                                       + bgq * 4 + bp * 2] = v;
                }
        __syncthreads();   // all warps done with gemm + hx regions

        // prefetch x(s+1): one bulk; overlaps epilogue + flag post + skew
        if (s + 1 < TT && tid == 0) {
            MBAR_EXPECT(mbx_b, 32768u);
            bulk_g2s(hx_b, &g_xt[dir][s + 1][bgrp][0][0], 32768u, mbx_b);
        }

        // epilogue: reduce 8 k-groups, gates, cell update (1 cell per thread)
        {
            unsigned long long s01 = 0ull, s23 = 0ull;
            #pragma unroll
            for (int q = 0; q < 8; ++q) {
                s01 = addf2(s01, red[((q * 16 + nl2) * 2 + 0) * 16 + bl]);
                s23 = addf2(s23, red[((q * 16 + nl2) * 2 + 1) * 16 + bl]);
            }
            float pi, pf, pg, po;
            unpack2(s01, pi, pf);
            unpack2(s23, pg, po);
            pi += bsv[nl2 * 4 + 0];
            pf += bsv[nl2 * 4 + 1];
            pg += bsv[nl2 * 4 + 2];
            po += bsv[nl2 * 4 + 3];

            float si = fsig(pi), sf = fsig(pf), tg = ftanh(pg), so = fsig(po);
            cth = sf * cth + si * tg;
            float hval = so * ftanh(cth);

            float2 hd; hd.x = hval; hd.y = hval;
            *(float2*)&g_hb[dir][p ^ 1][bgrp][n][bl * 2] = hd;

            __syncthreads();        // all h writes done before the release-store
            if (tid == 0) st_release(&g_flag[gid][nc][0], s + 2);

            if (s < L) {
                const int t = dir ? (L - 1 - s) : s;
                out[((size_t)myb * TT + t) * (2 * HH) + dir * HH + n] = hval;
            }
        }
        p ^= 1;
    }

    // final barrier, then reset flags for the next graph replay
    global_barrier(tid);
    if (tid == 0) *((volatile int*)&g_flag[gid][nc][0]) = 0;
}

extern "C" void kernel_launch(void* const* d_in, const int* in_sizes, int n_in,
                              void* d_out, int out_size) {
    const float* x     = (const float*)d_in[0];
    const int*   lens  = (const int*)  d_in[1];
    const float* Wih_f = (const float*)d_in[2];
    const float* Whh_f = (const float*)d_in[3];
    const float* bih_f = (const float*)d_in[4];
    const float* bhh_f = (const float*)d_in[5];
    const float* Wih_b = (const float*)d_in[6];
    const float* Whh_b = (const float*)d_in[7];
    const float* bih_b = (const float*)d_in[8];
    const float* bhh_b = (const float*)d_in[9];
    float* out = (float*)d_out;

    // zero the padded/masked region (output beyond input_length must be 0)
    cudaMemsetAsync(out, 0, (size_t)out_size * sizeof(float), 0);

    const size_t smem_bytes = (size_t)SMEM_FLOATS * sizeof(float);
    cudaFuncSetAttribute(bilstm_kernel,
                         cudaFuncAttributeMaxDynamicSharedMemorySize, (int)smem_bytes);

    bilstm_kernel<<<NBLK, NTHR, smem_bytes>>>(x, lens, Wih_f, Whh_f, bih_f, bhh_f,
                                              Wih_b, Whh_b, bih_b, bhh_b, out);
}